// round 13
// baseline (speedup 1.0000x reference)
#include <cuda_runtime.h>
#include <cuda_fp16.h>

#define NN 50000
#define EE 800000
#define ET (EE + NN)
#define FF 128
#define SLOPE 0.2f
#define EPSBN 1e-5f
#define NB1024 ((NN + 1023) / 1024)

// ---------------- scratch (device globals) -----------------------------------
__device__ __align__(16) __half g_hh[NN * FF];   // post-GEMM features (half)
__device__ __align__(16) float g_act[NN * FF];   // layer activations (fp32, pre-BN)
__device__ __align__(16) float g_als[NN * 2];    // src logits per head
__device__ __align__(16) float g_ald[NN * 2];    // dst logits per head
__device__ __align__(16) float g_sumA[2][FF];    // BN channel sums (per layer)
__device__ __align__(16) float g_sqA[2][FF];     // BN channel sum sq
__device__ int g_deg[NN];
__device__ int g_off[NN + 1];
__device__ int g_cur[NN];
__device__ int g_srcs[ET];
__device__ int g_bsum[64];
__device__ int g_is64;

// ---------------- detect dtype + zero degree + zero BN stats ------------------
__global__ void k_detect(const int* __restrict__ ei32) {
    int i = blockIdx.x * blockDim.x + threadIdx.x;
    if (i < NN) g_deg[i] = 0;
    if (blockIdx.x == 0) {
        if (threadIdx.x < FF) {
            g_sumA[0][threadIdx.x] = 0.f; g_sqA[0][threadIdx.x] = 0.f;
            g_sumA[1][threadIdx.x] = 0.f; g_sqA[1][threadIdx.x] = 0.f;
        }
        if (threadIdx.x < 32) {
            int acc = 0;
            for (int k = threadIdx.x; k < 2048; k += 32) acc |= ei32[2 * k + 1];
#pragma unroll
            for (int off = 16; off; off >>= 1)
                acc |= __shfl_xor_sync(0xffffffffu, acc, off);
            if (threadIdx.x == 0) g_is64 = (acc == 0) ? 1 : 0;
        }
    }
}

__device__ __forceinline__ void load_edge(const void* ei, int e, int& s, int& d) {
    if (e < EE) {
        if (g_is64) {
            const long long* e64 = (const long long*)ei;
            s = (int)e64[e]; d = (int)e64[EE + e];
        } else {
            const int* e32 = (const int*)ei;
            s = e32[e]; d = e32[EE + e];
        }
        s = min(max(s, 0), NN - 1);
        d = min(max(d, 0), NN - 1);
    } else {
        s = d = e - EE;
    }
}

__global__ void k_hist(const void* __restrict__ ei) {
    int e = blockIdx.x * blockDim.x + threadIdx.x;
    if (e >= ET) return;
    int s, d; load_edge(ei, e, s, d);
    atomicAdd(&g_deg[d], 1);
}

// ---------------- multi-block scan ---------------------------------------------
__global__ void __launch_bounds__(1024) k_scanA() {
    __shared__ int warpsum[32];
    int t = threadIdx.x, lane = t & 31, w = t >> 5;
    int i = blockIdx.x * 1024 + t;
    int v = (i < NN) ? g_deg[i] : 0;
    int x = v;
#pragma unroll
    for (int off = 1; off < 32; off <<= 1) {
        int y = __shfl_up_sync(0xffffffffu, x, off);
        if (lane >= off) x += y;
    }
    if (lane == 31) warpsum[w] = x;
    __syncthreads();
    if (w == 0) {
        int s = warpsum[lane];
#pragma unroll
        for (int off = 1; off < 32; off <<= 1) {
            int y = __shfl_up_sync(0xffffffffu, s, off);
            if (lane >= off) s += y;
        }
        warpsum[lane] = s;
    }
    __syncthreads();
    int wbase = (w > 0) ? warpsum[w - 1] : 0;
    int incl = x + wbase;
    if (i < NN) g_off[i] = incl - v;      // exclusive, block-local
    if (t == 1023) g_bsum[blockIdx.x] = incl;
}

// scanC: adds block offsets (computed redundantly per block) + init cursors
__global__ void k_scanC() {
    __shared__ int soff[64];
    int t = threadIdx.x;
    if (t < 64) {
        int v = (t < NB1024) ? g_bsum[t] : 0;
        int lane = t & 31;
        int x = v;
#pragma unroll
        for (int off = 1; off < 32; off <<= 1) {
            int y = __shfl_up_sync(0xffffffffu, x, off);
            if (lane >= off) x += y;
        }
        soff[t] = x - v;                  // exclusive within warp
    }
    __syncthreads();
    if (t >= 32 && t < 64) {
        int w0tot = soff[31] + ((31 < NB1024) ? g_bsum[31] : 0);
        soff[t] += w0tot;
    }
    __syncthreads();
    int i = blockIdx.x * blockDim.x + t;
    if (i < NN) {
        int off = g_off[i] + soff[i >> 10];
        g_off[i] = off;
        g_cur[i] = off;
    }
    if (i == 0) g_off[NN] = ET;
}

__global__ void k_scatter(const void* __restrict__ ei) {
    int e = blockIdx.x * blockDim.x + threadIdx.x;
    if (e >= ET) return;
    int s, d; load_edge(ei, e, s, d);
    int pos = atomicAdd(&g_cur[d], 1);
    g_srcs[pos] = s;
}

// ---------------- tf32 tensor-core GEMM, M-tile 128 ---------------------------
#define WS_STRIDE 136
#define AS_STRIDE 132
#define GEMM_SMEM ((128 * WS_STRIDE + 128 * AS_STRIDE) * 4)

__device__ __forceinline__ unsigned f2tf(float x) {
    unsigned u;
    asm("cvt.rna.tf32.f32 %0, %1;" : "=r"(u) : "f"(x));
    return u;
}

__device__ __forceinline__ void mma_tf32(float* d,
                                         unsigned a0, unsigned a1, unsigned a2,
                                         unsigned a3, unsigned b0, unsigned b1) {
    asm("mma.sync.aligned.m16n8k8.row.col.f32.tf32.tf32.f32 "
        "{%0,%1,%2,%3},{%4,%5,%6,%7},{%8,%9},{%0,%1,%2,%3};"
        : "+f"(d[0]), "+f"(d[1]), "+f"(d[2]), "+f"(d[3])
        : "r"(a0), "r"(a1), "r"(a2), "r"(a3), "r"(b0), "r"(b1));
}

__global__ void __launch_bounds__(256) k_gemm(const float* __restrict__ A,
                                              const float* __restrict__ W,
                                              const float* __restrict__ asrc,
                                              const float* __restrict__ adst,
                                              const float* __restrict__ bng,
                                              const float* __restrict__ bnb,
                                              int bnbuf) {
    extern __shared__ unsigned smem[];
    unsigned* Ws = smem;                          // [128][136]
    unsigned* As = smem + 128 * WS_STRIDE;        // [128][132]

    const float* Ap = A ? A : g_act;
    int t = threadIdx.x;
    int n0 = blockIdx.x * 128;

    {
        int c4 = (t & 31) * 4;
#pragma unroll
        for (int i = 0; i < 16; i++) {
            int k = (t >> 5) + i * 8;
            float4 w4 = *(const float4*)&W[k * 128 + c4];
            unsigned* dst = &Ws[k * WS_STRIDE + c4];
            dst[0] = f2tf(w4.x); dst[1] = f2tf(w4.y);
            dst[2] = f2tf(w4.z); dst[3] = f2tf(w4.w);
        }
    }
    {
        int c4 = (t & 31) * 4;
        float4 sc = make_float4(1.f, 1.f, 1.f, 1.f);
        float4 sh = make_float4(0.f, 0.f, 0.f, 0.f);
        bool bn = (bnbuf >= 0);
        if (bn) {
            const float invn = 1.f / (float)NN;
            float4 s = *(const float4*)&g_sumA[bnbuf][c4];
            float4 q = *(const float4*)&g_sqA[bnbuf][c4];
            float4 gg = *(const float4*)&bng[c4];
            float4 bb = *(const float4*)&bnb[c4];
            float mu, var, r;
            mu = s.x * invn; var = q.x * invn - mu * mu; r = rsqrtf(var + EPSBN) * gg.x;
            sc.x = r; sh.x = bb.x - mu * r;
            mu = s.y * invn; var = q.y * invn - mu * mu; r = rsqrtf(var + EPSBN) * gg.y;
            sc.y = r; sh.y = bb.y - mu * r;
            mu = s.z * invn; var = q.z * invn - mu * mu; r = rsqrtf(var + EPSBN) * gg.z;
            sc.z = r; sh.z = bb.z - mu * r;
            mu = s.w * invn; var = q.w * invn - mu * mu; r = rsqrtf(var + EPSBN) * gg.w;
            sc.w = r; sh.w = bb.w - mu * r;
        }
#pragma unroll
        for (int i = 0; i < 16; i++) {
            int r = (t >> 5) + i * 8;       // 0..127
            int row = n0 + r;
            float4 v = make_float4(0.f, 0.f, 0.f, 0.f);
            if (row < NN) v = *(const float4*)&Ap[row * 128 + c4];
            if (bn) {
                v.x = fmaxf(v.x * sc.x + sh.x, 0.f);
                v.y = fmaxf(v.y * sc.y + sh.y, 0.f);
                v.z = fmaxf(v.z * sc.z + sh.z, 0.f);
                v.w = fmaxf(v.w * sc.w + sh.w, 0.f);
            }
            unsigned* dst = &As[r * AS_STRIDE + c4];
            dst[0] = f2tf(v.x); dst[1] = f2tf(v.y);
            dst[2] = f2tf(v.z); dst[3] = f2tf(v.w);
        }
    }
    __syncthreads();

    int lane = t & 31, wid = t >> 5;
    int g = lane >> 2, tg = lane & 3;
    int mg = wid & 3, ng = wid >> 2;

    float accA[8][4], accB[8][4];
#pragma unroll
    for (int j = 0; j < 8; j++)
#pragma unroll
        for (int e = 0; e < 4; e++) { accA[j][e] = 0.f; accB[j][e] = 0.f; }

    const int rowA0 = (mg * 32 + g) * AS_STRIDE;
    const int rowA1 = rowA0 + 8 * AS_STRIDE;
    const int rowB0 = rowA0 + 16 * AS_STRIDE;
    const int rowB1 = rowA0 + 24 * AS_STRIDE;

#pragma unroll
    for (int kk = 0; kk < 16; kk++) {
        int kb = kk * 8;
        unsigned aA0 = As[rowA0 + kb + tg];
        unsigned aA1 = As[rowA1 + kb + tg];
        unsigned aA2 = As[rowA0 + kb + tg + 4];
        unsigned aA3 = As[rowA1 + kb + tg + 4];
        unsigned aB0 = As[rowB0 + kb + tg];
        unsigned aB1 = As[rowB1 + kb + tg];
        unsigned aB2 = As[rowB0 + kb + tg + 4];
        unsigned aB3 = As[rowB1 + kb + tg + 4];
#pragma unroll
        for (int j = 0; j < 8; j++) {
            int cb = ng * 64 + j * 8 + g;
            unsigned b0 = Ws[(kb + tg) * WS_STRIDE + cb];
            unsigned b1 = Ws[(kb + tg + 4) * WS_STRIDE + cb];
            mma_tf32(accA[j], aA0, aA1, aA2, aA3, b0, b1);
            mma_tf32(accB[j], aB0, aB1, aB2, aB3, b0, b1);
        }
    }

    int r0 = mg * 32 + g;
    float ps0 = 0.f, ps1 = 0.f, ps2 = 0.f, ps3 = 0.f;
    float pd0 = 0.f, pd1 = 0.f, pd2 = 0.f, pd3 = 0.f;
#pragma unroll
    for (int j = 0; j < 8; j++) {
        int cj = ng * 64 + j * 8 + 2 * tg;
        float asx = asrc[cj], asy = asrc[cj + 1];
        float adx = adst[cj], ady = adst[cj + 1];
        ps0 += accA[j][0] * asx + accA[j][1] * asy;
        pd0 += accA[j][0] * adx + accA[j][1] * ady;
        ps1 += accA[j][2] * asx + accA[j][3] * asy;
        pd1 += accA[j][2] * adx + accA[j][3] * ady;
        ps2 += accB[j][0] * asx + accB[j][1] * asy;
        pd2 += accB[j][0] * adx + accB[j][1] * ady;
        ps3 += accB[j][2] * asx + accB[j][3] * asy;
        pd3 += accB[j][2] * adx + accB[j][3] * ady;
        int row;
        row = n0 + r0;
        if (row < NN) *(__half2*)&g_hh[row * 128 + cj] = __floats2half2_rn(accA[j][0], accA[j][1]);
        row = n0 + r0 + 8;
        if (row < NN) *(__half2*)&g_hh[row * 128 + cj] = __floats2half2_rn(accA[j][2], accA[j][3]);
        row = n0 + r0 + 16;
        if (row < NN) *(__half2*)&g_hh[row * 128 + cj] = __floats2half2_rn(accB[j][0], accB[j][1]);
        row = n0 + r0 + 24;
        if (row < NN) *(__half2*)&g_hh[row * 128 + cj] = __floats2half2_rn(accB[j][2], accB[j][3]);
    }
#pragma unroll
    for (int off = 1; off <= 2; off <<= 1) {
        ps0 += __shfl_xor_sync(0xffffffffu, ps0, off);
        ps1 += __shfl_xor_sync(0xffffffffu, ps1, off);
        ps2 += __shfl_xor_sync(0xffffffffu, ps2, off);
        ps3 += __shfl_xor_sync(0xffffffffu, ps3, off);
        pd0 += __shfl_xor_sync(0xffffffffu, pd0, off);
        pd1 += __shfl_xor_sync(0xffffffffu, pd1, off);
        pd2 += __shfl_xor_sync(0xffffffffu, pd2, off);
        pd3 += __shfl_xor_sync(0xffffffffu, pd3, off);
    }
    if (tg == 0) {
        int row;
        row = n0 + r0;
        if (row < NN) { g_als[row * 2 + ng] = ps0; g_ald[row * 2 + ng] = pd0; }
        row = n0 + r0 + 8;
        if (row < NN) { g_als[row * 2 + ng] = ps1; g_ald[row * 2 + ng] = pd1; }
        row = n0 + r0 + 16;
        if (row < NN) { g_als[row * 2 + ng] = ps2; g_ald[row * 2 + ng] = pd2; }
        row = n0 + r0 + 24;
        if (row < NN) { g_als[row * 2 + ng] = ps3; g_ald[row * 2 + ng] = pd3; }
    }
}

// ---------------- aggregation core (warp per dst node, pipelined chunks) ------
// R11 structure (best known): 16-edge chunks; lanes 0-15 / 16-31 precompute
// head-0/head-1 weights for the SAME 16 edges; next chunk's loads prefetched
// before the broadcast loop; gathers via __ldg (read-only path).
#define AGGR_BODY(SRC, WV)                                                  \
    {                                                                       \
        int sj = __shfl_sync(0xffffffffu, SRC, j);                          \
        float wg = __shfl_sync(0xffffffffu, WV, j | wsrc);                  \
        uint2 u = __ldg((const uint2*)&g_hh[sj * 128 + c]);                 \
        float2 f0 = __half22float2(*(__half2*)&u.x);                        \
        float2 f1 = __half22float2(*(__half2*)&u.y);                        \
        a0 += wg * f0.x; a1 += wg * f0.y;                                   \
        a2 += wg * f1.x; a3 += wg * f1.y;                                   \
        den += wg;                                                          \
    }

__device__ __forceinline__ void aggr_node(int node, int lane, int hd, int c,
                                          float& a0, float& a1, float& a2,
                                          float& a3, float& den) {
    int beg = g_off[node], end = g_off[node + 1];
    float2 aldv = *(const float2*)&g_ald[node * 2];
    float aldh = hd ? aldv.y : aldv.x;
    int wsrc = lane & 16;
    int l = lane & 15;

    // prologue: chunk 0 srcs + weights
    int idx0 = beg + l;
    int sA = 0; float wA = 0.f;
    if (idx0 < end) {
        sA = __ldg(&g_srcs[idx0]);
        float e = __ldg(&g_als[sA * 2 + hd]) + aldh;
        e = (e > 0.f) ? e : SLOPE * e;
        wA = __expf(e);
    }

    for (int base = beg; base < end; base += 16) {
        int s_cur = sA; float w_cur = wA;
        // prefetch next chunk (loads overlap the broadcast below)
        int idx1 = base + 16 + l;
        bool v1 = idx1 < end;
        int sB = v1 ? __ldg(&g_srcs[idx1]) : 0;
        float alB = __ldg(&g_als[sB * 2 + hd]);

        int cnt = min(16, end - base);
        if (cnt == 16) {
#pragma unroll
            for (int j = 0; j < 16; j++) AGGR_BODY(s_cur, w_cur);
        } else {
            for (int j = 0; j < cnt; j++) AGGR_BODY(s_cur, w_cur);
        }

        // finish next chunk's weights
        float e = alB + aldh;
        e = (e > 0.f) ? e : SLOPE * e;
        wA = v1 ? __expf(e) : 0.f;
        sA = sB;
    }
}

// ---------------- fused aggregation (layers 0/1) + BN stats -------------------
__global__ void __launch_bounds__(256) k_aggr(const float* __restrict__ b,
                                              int statbuf) {
    __shared__ float ssum[FF], ssq[FF];
    int t = threadIdx.x, lane = t & 31, w = t >> 5;
    if (t < FF) { ssum[t] = 0.f; ssq[t] = 0.f; }
    __syncthreads();

    int node = blockIdx.x * 8 + w;
    int c = lane * 4;
    float v0 = 0.f, v1 = 0.f, v2 = 0.f, v3 = 0.f;
    if (node < NN) {
        int hd = lane >> 4;
        float a0 = 0.f, a1 = 0.f, a2 = 0.f, a3 = 0.f, den = 0.f;
        aggr_node(node, lane, hd, c, a0, a1, a2, a3, den);
        float inv = 1.f / (den + 1e-16f);
        float4 bb = *(const float4*)&b[c];
        v0 = a0 * inv + bb.x;
        v1 = a1 * inv + bb.y;
        v2 = a2 * inv + bb.z;
        v3 = a3 * inv + bb.w;
        *(float4*)&g_act[node * 128 + c] = make_float4(v0, v1, v2, v3);
    }
    atomicAdd(&ssum[c + 0], v0); atomicAdd(&ssq[c + 0], v0 * v0);
    atomicAdd(&ssum[c + 1], v1); atomicAdd(&ssq[c + 1], v1 * v1);
    atomicAdd(&ssum[c + 2], v2); atomicAdd(&ssq[c + 2], v2 * v2);
    atomicAdd(&ssum[c + 3], v3); atomicAdd(&ssq[c + 3], v3 * v3);
    __syncthreads();
    if (t < FF) {
        atomicAdd(&g_sumA[statbuf][t], ssum[t]);
        atomicAdd(&g_sqA[statbuf][t], ssq[t]);
    }
}

// ---------------- fused aggregation (layer 2): head-mean output ---------------
__global__ void __launch_bounds__(256) k_aggr_out(const float* __restrict__ b2,
                                                  float* __restrict__ out) {
    int t = threadIdx.x, lane = t & 31, w = t >> 5;
    int node = blockIdx.x * 8 + w;
    if (node >= NN) return;
    int c = lane * 4;
    int hd = lane >> 4;
    float a0 = 0.f, a1 = 0.f, a2 = 0.f, a3 = 0.f, den = 0.f;
    aggr_node(node, lane, hd, c, a0, a1, a2, a3, den);
    float inv = 1.f / (den + 1e-16f);
    float r0 = a0 * inv, r1 = a1 * inv, r2 = a2 * inv, r3 = a3 * inv;
    r0 = 0.5f * (r0 + __shfl_xor_sync(0xffffffffu, r0, 16));
    r1 = 0.5f * (r1 + __shfl_xor_sync(0xffffffffu, r1, 16));
    r2 = 0.5f * (r2 + __shfl_xor_sync(0xffffffffu, r2, 16));
    r3 = 0.5f * (r3 + __shfl_xor_sync(0xffffffffu, r3, 16));
    if (lane < 16) {
        float4 bb = *(const float4*)&b2[c];
        *(float4*)&out[node * 64 + c] =
            make_float4(r0 + bb.x, r1 + bb.y, r2 + bb.z, r3 + bb.w);
    }
}

// ---------------- launch -----------------------------------------------------
extern "C" void kernel_launch(void* const* d_in, const int* in_sizes, int n_in,
                              void* d_out, int out_size) {
    (void)in_sizes; (void)n_in; (void)out_size;
    const float* x      = (const float*)d_in[0];
    const void*  ei     = d_in[1];
    const float* W0  = (const float*)d_in[2];
    const float* as0 = (const float*)d_in[3];
    const float* ad0 = (const float*)d_in[4];
    const float* b0  = (const float*)d_in[5];
    const float* g0  = (const float*)d_in[6];
    const float* be0 = (const float*)d_in[7];
    const float* W1  = (const float*)d_in[8];
    const float* as1 = (const float*)d_in[9];
    const float* ad1 = (const float*)d_in[10];
    const float* b1  = (const float*)d_in[11];
    const float* g1  = (const float*)d_in[12];
    const float* be1 = (const float*)d_in[13];
    const float* W2  = (const float*)d_in[14];
    const float* as2 = (const float*)d_in[15];
    const float* ad2 = (const float*)d_in[16];
    const float* b2  = (const float*)d_in[17];
    float* out = (float*)d_out;

    cudaFuncSetAttribute(k_gemm, cudaFuncAttributeMaxDynamicSharedMemorySize,
                         GEMM_SMEM);

    const int GB  = (NN + 127) / 128;
    const int NB  = (NN + 255) / 256;
    const int EB  = (ET + 255) / 256;
    const int AB  = (NN + 7) / 8;

    // fork-join: CSR build runs concurrently with layer-0 GEMM
    cudaStream_t side;
    cudaStreamCreateWithFlags(&side, cudaStreamNonBlocking);
    cudaEvent_t evF, evJ;
    cudaEventCreateWithFlags(&evF, cudaEventDisableTiming);
    cudaEventCreateWithFlags(&evJ, cudaEventDisableTiming);

    cudaEventRecord(evF, 0);
    cudaStreamWaitEvent(side, evF, 0);

    // ---- CSR build (side stream) ----
    k_detect<<<NB, 256, 0, side>>>((const int*)ei);
    k_hist<<<EB, 256, 0, side>>>(ei);
    k_scanA<<<NB1024, 1024, 0, side>>>();
    k_scanC<<<NB, 256, 0, side>>>();
    k_scatter<<<EB, 256, 0, side>>>(ei);
    cudaEventRecord(evJ, side);

    // ---- layer 0 GEMM (default stream, concurrent with CSR) ----
    k_gemm<<<GB, 256, GEMM_SMEM>>>(x, W0, as0, ad0, nullptr, nullptr, -1);

    cudaStreamWaitEvent(0, evJ, 0);

    // ---- layer 0 aggregation ----
    k_aggr<<<AB, 256>>>(b0, 0);

    // ---- layer 1 (BN0 fused into A-load) ----
    k_gemm<<<GB, 256, GEMM_SMEM>>>(nullptr, W1, as1, ad1, g0, be0, 0);
    k_aggr<<<AB, 256>>>(b1, 1);

    // ---- layer 2 (BN1 fused into A-load, head-mean out) ----
    k_gemm<<<GB, 256, GEMM_SMEM>>>(nullptr, W2, as2, ad2, g1, be1, 1);
    k_aggr_out<<<AB, 256>>>(b2, out);

    cudaEventDestroy(evF);
    cudaEventDestroy(evJ);
    cudaStreamDestroy(side);
}

// round 14
// speedup vs baseline: 1.4862x; 1.4862x over previous
#include <cuda_runtime.h>
#include <cuda_fp16.h>

#define NN 50000
#define EE 800000
#define ET (EE + NN)
#define FF 128
#define SLOPE 0.2f
#define EPSBN 1e-5f
#define NB1024 ((NN + 1023) / 1024)

// ---------------- scratch (device globals) -----------------------------------
__device__ __align__(16) __half g_hh[NN * FF];   // post-GEMM features (half)
__device__ __align__(16) float g_act[NN * FF];   // layer activations (fp32, pre-BN)
__device__ __align__(16) float g_als[NN * 2];    // src logits per head
__device__ __align__(16) float g_ald[NN * 2];    // dst logits per head
__device__ __align__(16) float g_sumA[2][FF];    // BN channel sums (per layer)
__device__ __align__(16) float g_sqA[2][FF];     // BN channel sum sq
__device__ int g_deg[NN];
__device__ int g_off[NN + 1];
__device__ int g_cur[NN];
__device__ int g_srcs[ET];
__device__ int g_bsum[64];
__device__ int g_is64;

// ---------------- detect dtype + zero degree + zero BN stats ------------------
__global__ void k_detect(const int* __restrict__ ei32) {
    int i = blockIdx.x * blockDim.x + threadIdx.x;
    if (i < NN) g_deg[i] = 0;
    if (blockIdx.x == 0) {
        if (threadIdx.x < FF) {
            g_sumA[0][threadIdx.x] = 0.f; g_sqA[0][threadIdx.x] = 0.f;
            g_sumA[1][threadIdx.x] = 0.f; g_sqA[1][threadIdx.x] = 0.f;
        }
        if (threadIdx.x < 32) {
            int acc = 0;
            for (int k = threadIdx.x; k < 2048; k += 32) acc |= ei32[2 * k + 1];
#pragma unroll
            for (int off = 16; off; off >>= 1)
                acc |= __shfl_xor_sync(0xffffffffu, acc, off);
            if (threadIdx.x == 0) g_is64 = (acc == 0) ? 1 : 0;
        }
    }
}

__device__ __forceinline__ void load_edge(const void* ei, int e, int& s, int& d) {
    if (e < EE) {
        if (g_is64) {
            const long long* e64 = (const long long*)ei;
            s = (int)e64[e]; d = (int)e64[EE + e];
        } else {
            const int* e32 = (const int*)ei;
            s = e32[e]; d = e32[EE + e];
        }
        s = min(max(s, 0), NN - 1);
        d = min(max(d, 0), NN - 1);
    } else {
        s = d = e - EE;
    }
}

__global__ void k_hist(const void* __restrict__ ei) {
    int e = blockIdx.x * blockDim.x + threadIdx.x;
    if (e >= ET) return;
    int s, d; load_edge(ei, e, s, d);
    atomicAdd(&g_deg[d], 1);
}

// ---------------- multi-block scan ---------------------------------------------
__global__ void __launch_bounds__(1024) k_scanA() {
    __shared__ int warpsum[32];
    int t = threadIdx.x, lane = t & 31, w = t >> 5;
    int i = blockIdx.x * 1024 + t;
    int v = (i < NN) ? g_deg[i] : 0;
    int x = v;
#pragma unroll
    for (int off = 1; off < 32; off <<= 1) {
        int y = __shfl_up_sync(0xffffffffu, x, off);
        if (lane >= off) x += y;
    }
    if (lane == 31) warpsum[w] = x;
    __syncthreads();
    if (w == 0) {
        int s = warpsum[lane];
#pragma unroll
        for (int off = 1; off < 32; off <<= 1) {
            int y = __shfl_up_sync(0xffffffffu, s, off);
            if (lane >= off) s += y;
        }
        warpsum[lane] = s;
    }
    __syncthreads();
    int wbase = (w > 0) ? warpsum[w - 1] : 0;
    int incl = x + wbase;
    if (i < NN) g_off[i] = incl - v;      // exclusive, block-local
    if (t == 1023) g_bsum[blockIdx.x] = incl;
}

// scanC: adds block offsets (computed redundantly per block) + init cursors
__global__ void k_scanC() {
    __shared__ int soff[64];
    int t = threadIdx.x;
    if (t < 64) {
        int v = (t < NB1024) ? g_bsum[t] : 0;
        int lane = t & 31;
        int x = v;
#pragma unroll
        for (int off = 1; off < 32; off <<= 1) {
            int y = __shfl_up_sync(0xffffffffu, x, off);
            if (lane >= off) x += y;
        }
        soff[t] = x - v;                  // exclusive within warp
    }
    __syncthreads();
    if (t >= 32 && t < 64) {
        int w0tot = soff[31] + ((31 < NB1024) ? g_bsum[31] : 0);
        soff[t] += w0tot;
    }
    __syncthreads();
    int i = blockIdx.x * blockDim.x + t;
    if (i < NN) {
        int off = g_off[i] + soff[i >> 10];
        g_off[i] = off;
        g_cur[i] = off;
    }
    if (i == 0) g_off[NN] = ET;
}

__global__ void k_scatter(const void* __restrict__ ei) {
    int e = blockIdx.x * blockDim.x + threadIdx.x;
    if (e >= ET) return;
    int s, d; load_edge(ei, e, s, d);
    int pos = atomicAdd(&g_cur[d], 1);
    g_srcs[pos] = s;
}

// ---------------- tf32 tensor-core GEMM, M-tile 128 ---------------------------
#define WS_STRIDE 136
#define AS_STRIDE 132
#define GEMM_SMEM ((128 * WS_STRIDE + 128 * AS_STRIDE) * 4)

__device__ __forceinline__ unsigned f2tf(float x) {
    unsigned u;
    asm("cvt.rna.tf32.f32 %0, %1;" : "=r"(u) : "f"(x));
    return u;
}

__device__ __forceinline__ void mma_tf32(float* d,
                                         unsigned a0, unsigned a1, unsigned a2,
                                         unsigned a3, unsigned b0, unsigned b1) {
    asm("mma.sync.aligned.m16n8k8.row.col.f32.tf32.tf32.f32 "
        "{%0,%1,%2,%3},{%4,%5,%6,%7},{%8,%9},{%0,%1,%2,%3};"
        : "+f"(d[0]), "+f"(d[1]), "+f"(d[2]), "+f"(d[3])
        : "r"(a0), "r"(a1), "r"(a2), "r"(a3), "r"(b0), "r"(b1));
}

__global__ void __launch_bounds__(256) k_gemm(const float* __restrict__ A,
                                              const float* __restrict__ W,
                                              const float* __restrict__ asrc,
                                              const float* __restrict__ adst,
                                              const float* __restrict__ bng,
                                              const float* __restrict__ bnb,
                                              int bnbuf) {
    extern __shared__ unsigned smem[];
    unsigned* Ws = smem;                          // [128][136]
    unsigned* As = smem + 128 * WS_STRIDE;        // [128][132]

    const float* Ap = A ? A : g_act;
    int t = threadIdx.x;
    int n0 = blockIdx.x * 128;

    {
        int c4 = (t & 31) * 4;
#pragma unroll
        for (int i = 0; i < 16; i++) {
            int k = (t >> 5) + i * 8;
            float4 w4 = *(const float4*)&W[k * 128 + c4];
            unsigned* dst = &Ws[k * WS_STRIDE + c4];
            dst[0] = f2tf(w4.x); dst[1] = f2tf(w4.y);
            dst[2] = f2tf(w4.z); dst[3] = f2tf(w4.w);
        }
    }
    {
        int c4 = (t & 31) * 4;
        float4 sc = make_float4(1.f, 1.f, 1.f, 1.f);
        float4 sh = make_float4(0.f, 0.f, 0.f, 0.f);
        bool bn = (bnbuf >= 0);
        if (bn) {
            const float invn = 1.f / (float)NN;
            float4 s = *(const float4*)&g_sumA[bnbuf][c4];
            float4 q = *(const float4*)&g_sqA[bnbuf][c4];
            float4 gg = *(const float4*)&bng[c4];
            float4 bb = *(const float4*)&bnb[c4];
            float mu, var, r;
            mu = s.x * invn; var = q.x * invn - mu * mu; r = rsqrtf(var + EPSBN) * gg.x;
            sc.x = r; sh.x = bb.x - mu * r;
            mu = s.y * invn; var = q.y * invn - mu * mu; r = rsqrtf(var + EPSBN) * gg.y;
            sc.y = r; sh.y = bb.y - mu * r;
            mu = s.z * invn; var = q.z * invn - mu * mu; r = rsqrtf(var + EPSBN) * gg.z;
            sc.z = r; sh.z = bb.z - mu * r;
            mu = s.w * invn; var = q.w * invn - mu * mu; r = rsqrtf(var + EPSBN) * gg.w;
            sc.w = r; sh.w = bb.w - mu * r;
        }
#pragma unroll
        for (int i = 0; i < 16; i++) {
            int r = (t >> 5) + i * 8;       // 0..127
            int row = n0 + r;
            float4 v = make_float4(0.f, 0.f, 0.f, 0.f);
            if (row < NN) v = *(const float4*)&Ap[row * 128 + c4];
            if (bn) {
                v.x = fmaxf(v.x * sc.x + sh.x, 0.f);
                v.y = fmaxf(v.y * sc.y + sh.y, 0.f);
                v.z = fmaxf(v.z * sc.z + sh.z, 0.f);
                v.w = fmaxf(v.w * sc.w + sh.w, 0.f);
            }
            unsigned* dst = &As[r * AS_STRIDE + c4];
            dst[0] = f2tf(v.x); dst[1] = f2tf(v.y);
            dst[2] = f2tf(v.z); dst[3] = f2tf(v.w);
        }
    }
    __syncthreads();

    int lane = t & 31, wid = t >> 5;
    int g = lane >> 2, tg = lane & 3;
    int mg = wid & 3, ng = wid >> 2;

    float accA[8][4], accB[8][4];
#pragma unroll
    for (int j = 0; j < 8; j++)
#pragma unroll
        for (int e = 0; e < 4; e++) { accA[j][e] = 0.f; accB[j][e] = 0.f; }

    const int rowA0 = (mg * 32 + g) * AS_STRIDE;
    const int rowA1 = rowA0 + 8 * AS_STRIDE;
    const int rowB0 = rowA0 + 16 * AS_STRIDE;
    const int rowB1 = rowA0 + 24 * AS_STRIDE;

#pragma unroll
    for (int kk = 0; kk < 16; kk++) {
        int kb = kk * 8;
        unsigned aA0 = As[rowA0 + kb + tg];
        unsigned aA1 = As[rowA1 + kb + tg];
        unsigned aA2 = As[rowA0 + kb + tg + 4];
        unsigned aA3 = As[rowA1 + kb + tg + 4];
        unsigned aB0 = As[rowB0 + kb + tg];
        unsigned aB1 = As[rowB1 + kb + tg];
        unsigned aB2 = As[rowB0 + kb + tg + 4];
        unsigned aB3 = As[rowB1 + kb + tg + 4];
#pragma unroll
        for (int j = 0; j < 8; j++) {
            int cb = ng * 64 + j * 8 + g;
            unsigned b0 = Ws[(kb + tg) * WS_STRIDE + cb];
            unsigned b1 = Ws[(kb + tg + 4) * WS_STRIDE + cb];
            mma_tf32(accA[j], aA0, aA1, aA2, aA3, b0, b1);
            mma_tf32(accB[j], aB0, aB1, aB2, aB3, b0, b1);
        }
    }

    int r0 = mg * 32 + g;
    float ps0 = 0.f, ps1 = 0.f, ps2 = 0.f, ps3 = 0.f;
    float pd0 = 0.f, pd1 = 0.f, pd2 = 0.f, pd3 = 0.f;
#pragma unroll
    for (int j = 0; j < 8; j++) {
        int cj = ng * 64 + j * 8 + 2 * tg;
        float asx = asrc[cj], asy = asrc[cj + 1];
        float adx = adst[cj], ady = adst[cj + 1];
        ps0 += accA[j][0] * asx + accA[j][1] * asy;
        pd0 += accA[j][0] * adx + accA[j][1] * ady;
        ps1 += accA[j][2] * asx + accA[j][3] * asy;
        pd1 += accA[j][2] * adx + accA[j][3] * ady;
        ps2 += accB[j][0] * asx + accB[j][1] * asy;
        pd2 += accB[j][0] * adx + accB[j][1] * ady;
        ps3 += accB[j][2] * asx + accB[j][3] * asy;
        pd3 += accB[j][2] * adx + accB[j][3] * ady;
        int row;
        row = n0 + r0;
        if (row < NN) *(__half2*)&g_hh[row * 128 + cj] = __floats2half2_rn(accA[j][0], accA[j][1]);
        row = n0 + r0 + 8;
        if (row < NN) *(__half2*)&g_hh[row * 128 + cj] = __floats2half2_rn(accA[j][2], accA[j][3]);
        row = n0 + r0 + 16;
        if (row < NN) *(__half2*)&g_hh[row * 128 + cj] = __floats2half2_rn(accB[j][0], accB[j][1]);
        row = n0 + r0 + 24;
        if (row < NN) *(__half2*)&g_hh[row * 128 + cj] = __floats2half2_rn(accB[j][2], accB[j][3]);
    }
#pragma unroll
    for (int off = 1; off <= 2; off <<= 1) {
        ps0 += __shfl_xor_sync(0xffffffffu, ps0, off);
        ps1 += __shfl_xor_sync(0xffffffffu, ps1, off);
        ps2 += __shfl_xor_sync(0xffffffffu, ps2, off);
        ps3 += __shfl_xor_sync(0xffffffffu, ps3, off);
        pd0 += __shfl_xor_sync(0xffffffffu, pd0, off);
        pd1 += __shfl_xor_sync(0xffffffffu, pd1, off);
        pd2 += __shfl_xor_sync(0xffffffffu, pd2, off);
        pd3 += __shfl_xor_sync(0xffffffffu, pd3, off);
    }
    if (tg == 0) {
        int row;
        row = n0 + r0;
        if (row < NN) { g_als[row * 2 + ng] = ps0; g_ald[row * 2 + ng] = pd0; }
        row = n0 + r0 + 8;
        if (row < NN) { g_als[row * 2 + ng] = ps1; g_ald[row * 2 + ng] = pd1; }
        row = n0 + r0 + 16;
        if (row < NN) { g_als[row * 2 + ng] = ps2; g_ald[row * 2 + ng] = pd2; }
        row = n0 + r0 + 24;
        if (row < NN) { g_als[row * 2 + ng] = ps3; g_ald[row * 2 + ng] = pd3; }
    }
}

// ---------------- aggregation core (warp per dst node, pipelined chunks) ------
// 16-edge chunks; lanes 0-15 / 16-31 precompute head-0/head-1 weights for the
// SAME 16 edges. Next chunk's g_srcs + g_als loads are issued BEFORE the
// current chunk's broadcast loop, hiding the ~470-cycle dependent-load chain
// behind ~800 cycles of broadcast work. Full chunks take an unrolled fast path.
#define AGGR_BODY(SRC, WV)                                                  \
    {                                                                       \
        int sj = __shfl_sync(0xffffffffu, SRC, j);                          \
        float wg = __shfl_sync(0xffffffffu, WV, j | wsrc);                  \
        uint2 u = *(const uint2*)&g_hh[sj * 128 + c];                       \
        float2 f0 = __half22float2(*(__half2*)&u.x);                        \
        float2 f1 = __half22float2(*(__half2*)&u.y);                        \
        a0 += wg * f0.x; a1 += wg * f0.y;                                   \
        a2 += wg * f1.x; a3 += wg * f1.y;                                   \
        den += wg;                                                          \
    }

__device__ __forceinline__ void aggr_node(int node, int lane, int hd, int c,
                                          float& a0, float& a1, float& a2,
                                          float& a3, float& den) {
    int beg = g_off[node], end = g_off[node + 1];
    float2 aldv = *(const float2*)&g_ald[node * 2];
    float aldh = hd ? aldv.y : aldv.x;
    int wsrc = lane & 16;
    int l = lane & 15;

    // prologue: chunk 0 srcs + weights
    int idx0 = beg + l;
    int sA = 0; float wA = 0.f;
    if (idx0 < end) {
        sA = g_srcs[idx0];
        float e = g_als[sA * 2 + hd] + aldh;
        e = (e > 0.f) ? e : SLOPE * e;
        wA = __expf(e);
    }

    for (int base = beg; base < end; base += 16) {
        int s_cur = sA; float w_cur = wA;
        // prefetch next chunk (loads overlap the broadcast below)
        int idx1 = base + 16 + l;
        bool v1 = idx1 < end;
        int sB = v1 ? g_srcs[idx1] : 0;
        float alB = g_als[sB * 2 + hd];

        int cnt = min(16, end - base);
        if (cnt == 16) {
#pragma unroll
            for (int j = 0; j < 16; j++) AGGR_BODY(s_cur, w_cur);
        } else {
            for (int j = 0; j < cnt; j++) AGGR_BODY(s_cur, w_cur);
        }

        // finish next chunk's weights
        float e = alB + aldh;
        e = (e > 0.f) ? e : SLOPE * e;
        wA = v1 ? __expf(e) : 0.f;
        sA = sB;
    }
}

// ---------------- fused aggregation (layers 0/1) + BN stats -------------------
__global__ void __launch_bounds__(256) k_aggr(const float* __restrict__ b,
                                              int statbuf) {
    __shared__ float ssum[FF], ssq[FF];
    int t = threadIdx.x, lane = t & 31, w = t >> 5;
    if (t < FF) { ssum[t] = 0.f; ssq[t] = 0.f; }
    __syncthreads();

    int node = blockIdx.x * 8 + w;
    int c = lane * 4;
    float v0 = 0.f, v1 = 0.f, v2 = 0.f, v3 = 0.f;
    if (node < NN) {
        int hd = lane >> 4;
        float a0 = 0.f, a1 = 0.f, a2 = 0.f, a3 = 0.f, den = 0.f;
        aggr_node(node, lane, hd, c, a0, a1, a2, a3, den);
        float inv = 1.f / (den + 1e-16f);
        float4 bb = *(const float4*)&b[c];
        v0 = a0 * inv + bb.x;
        v1 = a1 * inv + bb.y;
        v2 = a2 * inv + bb.z;
        v3 = a3 * inv + bb.w;
        *(float4*)&g_act[node * 128 + c] = make_float4(v0, v1, v2, v3);
    }
    atomicAdd(&ssum[c + 0], v0); atomicAdd(&ssq[c + 0], v0 * v0);
    atomicAdd(&ssum[c + 1], v1); atomicAdd(&ssq[c + 1], v1 * v1);
    atomicAdd(&ssum[c + 2], v2); atomicAdd(&ssq[c + 2], v2 * v2);
    atomicAdd(&ssum[c + 3], v3); atomicAdd(&ssq[c + 3], v3 * v3);
    __syncthreads();
    if (t < FF) {
        atomicAdd(&g_sumA[statbuf][t], ssum[t]);
        atomicAdd(&g_sqA[statbuf][t], ssq[t]);
    }
}

// ---------------- fused aggregation (layer 2): head-mean output ---------------
__global__ void __launch_bounds__(256) k_aggr_out(const float* __restrict__ b2,
                                                  float* __restrict__ out) {
    int t = threadIdx.x, lane = t & 31, w = t >> 5;
    int node = blockIdx.x * 8 + w;
    if (node >= NN) return;
    int c = lane * 4;
    int hd = lane >> 4;
    float a0 = 0.f, a1 = 0.f, a2 = 0.f, a3 = 0.f, den = 0.f;
    aggr_node(node, lane, hd, c, a0, a1, a2, a3, den);
    float inv = 1.f / (den + 1e-16f);
    float r0 = a0 * inv, r1 = a1 * inv, r2 = a2 * inv, r3 = a3 * inv;
    r0 = 0.5f * (r0 + __shfl_xor_sync(0xffffffffu, r0, 16));
    r1 = 0.5f * (r1 + __shfl_xor_sync(0xffffffffu, r1, 16));
    r2 = 0.5f * (r2 + __shfl_xor_sync(0xffffffffu, r2, 16));
    r3 = 0.5f * (r3 + __shfl_xor_sync(0xffffffffu, r3, 16));
    if (lane < 16) {
        float4 bb = *(const float4*)&b2[c];
        *(float4*)&out[node * 64 + c] =
            make_float4(r0 + bb.x, r1 + bb.y, r2 + bb.z, r3 + bb.w);
    }
}

// ---------------- launch -----------------------------------------------------
extern "C" void kernel_launch(void* const* d_in, const int* in_sizes, int n_in,
                              void* d_out, int out_size) {
    (void)in_sizes; (void)n_in; (void)out_size;
    const float* x      = (const float*)d_in[0];
    const void*  ei     = d_in[1];
    const float* W0  = (const float*)d_in[2];
    const float* as0 = (const float*)d_in[3];
    const float* ad0 = (const float*)d_in[4];
    const float* b0  = (const float*)d_in[5];
    const float* g0  = (const float*)d_in[6];
    const float* be0 = (const float*)d_in[7];
    const float* W1  = (const float*)d_in[8];
    const float* as1 = (const float*)d_in[9];
    const float* ad1 = (const float*)d_in[10];
    const float* b1  = (const float*)d_in[11];
    const float* g1  = (const float*)d_in[12];
    const float* be1 = (const float*)d_in[13];
    const float* W2  = (const float*)d_in[14];
    const float* as2 = (const float*)d_in[15];
    const float* ad2 = (const float*)d_in[16];
    const float* b2  = (const float*)d_in[17];
    float* out = (float*)d_out;

    cudaFuncSetAttribute(k_gemm, cudaFuncAttributeMaxDynamicSharedMemorySize,
                         GEMM_SMEM);

    const int GB  = (NN + 127) / 128;
    const int NB  = (NN + 255) / 256;
    const int EB  = (ET + 255) / 256;
    const int AB  = (NN + 7) / 8;

    // fork-join: CSR build runs concurrently with layer-0 GEMM
    cudaStream_t side;
    cudaStreamCreateWithFlags(&side, cudaStreamNonBlocking);
    cudaEvent_t evF, evJ;
    cudaEventCreateWithFlags(&evF, cudaEventDisableTiming);
    cudaEventCreateWithFlags(&evJ, cudaEventDisableTiming);

    cudaEventRecord(evF, 0);
    cudaStreamWaitEvent(side, evF, 0);

    // ---- CSR build (side stream) ----
    k_detect<<<NB, 256, 0, side>>>((const int*)ei);
    k_hist<<<EB, 256, 0, side>>>(ei);
    k_scanA<<<NB1024, 1024, 0, side>>>();
    k_scanC<<<NB, 256, 0, side>>>();
    k_scatter<<<EB, 256, 0, side>>>(ei);
    cudaEventRecord(evJ, side);

    // ---- layer 0 GEMM (default stream, concurrent with CSR) ----
    k_gemm<<<GB, 256, GEMM_SMEM>>>(x, W0, as0, ad0, nullptr, nullptr, -1);

    cudaStreamWaitEvent(0, evJ, 0);

    // ---- layer 0 aggregation ----
    k_aggr<<<AB, 256>>>(b0, 0);

    // ---- layer 1 (BN0 fused into A-load) ----
    k_gemm<<<GB, 256, GEMM_SMEM>>>(nullptr, W1, as1, ad1, g0, be0, 0);
    k_aggr<<<AB, 256>>>(b1, 1);

    // ---- layer 2 (BN1 fused into A-load, head-mean out) ----
    k_gemm<<<GB, 256, GEMM_SMEM>>>(nullptr, W2, as2, ad2, g1, be1, 1);
    k_aggr_out<<<AB, 256>>>(b2, out);

    cudaEventDestroy(evF);
    cudaEventDestroy(evJ);
    cudaStreamDestroy(side);
}